// round 1
// baseline (speedup 1.0000x reference)
#include <cuda_runtime.h>
#include <cuda_bf16.h>

// SM-2 spaced-repetition scan.
// inputs: d_in[0] = (512, batch, 2) float32, d_in[1] = w (6) float32
// output: d_out = outputs (512, batch, 3) followed by final_state (batch, 3)

#define SEQ 512

__global__ __launch_bounds__(32) void SM2_31585189494808_kernel(
    const float2* __restrict__ in,   // (SEQ, batch) of float2 (we use .y = rating)
    const float*  __restrict__ w,    // 6 weights
    float*        __restrict__ out,  // SEQ*batch*3 outputs, then batch*3 final
    int batch)
{
    int b = blockIdx.x * 32 + threadIdx.x;
    if (b >= batch) return;

    const float w0 = __ldg(w + 0);
    const float w1 = __ldg(w + 1);
    const float w2 = __ldg(w + 2);
    const float w3 = __ldg(w + 3);
    const float w4 = __ldg(w + 4);
    const float w5 = __ldg(w + 5);

    float ivl  = 0.0f;
    float ef   = w2;
    float reps = 0.0f;

    const float2* pin = in + b;
    float* po = out + (size_t)b * 3;
    const size_t ostride = (size_t)batch * 3;

    // Software pipeline: keep a chunk of 4 ratings in flight one iteration ahead.
    float r[4];
#pragma unroll
    for (int j = 0; j < 4; ++j)
        r[j] = __ldg(&pin[(size_t)j * batch]).y;

    for (int t0 = 0; t0 < SEQ; t0 += 4) {
        float rn[4] = {0.f, 0.f, 0.f, 0.f};
        if (t0 + 4 < SEQ) {
#pragma unroll
            for (int j = 0; j < 4; ++j)
                rn[j] = __ldg(&pin[(size_t)(t0 + 4 + j) * batch]).y;
        }

#pragma unroll
        for (int j = 0; j < 4; ++j) {
            const float rating = r[j];

            const float nreps = (rating > 1.0f) ? (reps + 1.0f) : 1.0f;
            // NOTE: uses OLD ef, matching the reference.
            float nivl = (nreps == 1.0f) ? w0
                       : ((nreps == 2.0f) ? w1 : ivl * ef);
            const float q = rating + 1.0f;
            const float d = q - w4;
            float nef = (ef - w3 * (d * d)) + w5;

            nivl = fminf(fmaxf(nivl, 0.01f), 36500.0f);
            nef  = fminf(fmaxf(nef, 1.3f), 10.0f);

            float* o = po + (size_t)(t0 + j) * ostride;
            o[0] = nivl;
            o[1] = nef;
            o[2] = nreps;

            ivl = nivl; ef = nef; reps = nreps;
        }

#pragma unroll
        for (int j = 0; j < 4; ++j) r[j] = rn[j];
    }

    // final_state appended after the per-step outputs
    float* f = out + (size_t)SEQ * ostride + (size_t)b * 3;
    f[0] = ivl;
    f[1] = ef;
    f[2] = reps;
}

extern "C" void kernel_launch(void* const* d_in, const int* in_sizes, int n_in,
                              void* d_out, int out_size) {
    const float2* in = (const float2*)d_in[0];
    const float*  w  = (const float*)d_in[1];
    float* out = (float*)d_out;

    const int batch = in_sizes[0] / (SEQ * 2);
    const int grid = (batch + 31) / 32;

    SM2_31585189494808_kernel<<<grid, 32>>>(in, w, out, batch);
}

// round 2
// speedup vs baseline: 1.5670x; 1.5670x over previous
#include <cuda_runtime.h>
#include <cuda_bf16.h>

// SM-2 spaced-repetition scan.
// d_in[0] = (512, batch, 2) float32 (rating = [...,1]), d_in[1] = w (6) float32
// d_out   = outputs (512, batch, 3) followed by final_state (batch, 3)

#define SEQ 512
#define PF  16   // prefetch ring depth (one super-iteration ahead)

__global__ __launch_bounds__(32) void SM2_31585189494808_kernel(
    const float* __restrict__ in,   // (SEQ, batch, 2)
    const float* __restrict__ w,
    float*       __restrict__ out,
    int batch)
{
    const int b = blockIdx.x * 32 + threadIdx.x;
    if (b >= batch) return;

    const float w0 = __ldg(w + 0);
    const float w1 = __ldg(w + 1);
    const float w2 = __ldg(w + 2);
    const float w3 = __ldg(w + 3);
    const float w4 = __ldg(w + 4);
    const float w5 = __ldg(w + 5);

    float ivl  = 0.0f;
    float ef   = w2;
    float reps = 0.0f;

    // pointer to rating (.y) of column b at t=0
    const float* pin = in + (size_t)b * 2 + 1;
    const size_t istride = (size_t)batch * 2;

    float* po = out + (size_t)b * 3;
    const size_t ostride = (size_t)batch * 3;

    // Prefetch ring: PF ratings in flight, issued one super-iteration ahead.
    float r[PF];
#pragma unroll
    for (int j = 0; j < PF; ++j)
        r[j] = __ldcs(pin + (size_t)j * istride);

    for (int t0 = 0; t0 < SEQ; t0 += PF) {
        float rn[PF];
        if (t0 + PF < SEQ) {
#pragma unroll
            for (int j = 0; j < PF; ++j)
                rn[j] = __ldcs(pin + (size_t)(t0 + PF + j) * istride);
        } else {
#pragma unroll
            for (int j = 0; j < PF; ++j) rn[j] = 0.0f;
        }

#pragma unroll
        for (int j = 0; j < PF; ++j) {
            const float rating = r[j];

            const float nreps = (rating > 1.0f) ? (reps + 1.0f) : 1.0f;
            // NOTE: uses OLD ef, matching the reference.
            float nivl = (nreps == 1.0f) ? w0
                       : ((nreps == 2.0f) ? w1 : ivl * ef);
            const float q = rating + 1.0f;
            const float d = q - w4;
            float nef = (ef - w3 * (d * d)) + w5;

            nivl = fminf(fmaxf(nivl, 0.01f), 36500.0f);
            nef  = fminf(fmaxf(nef, 1.3f), 10.0f);

            float* o = po + (size_t)(t0 + j) * ostride;
            __stcs(o + 0, nivl);
            __stcs(o + 1, nef);
            __stcs(o + 2, nreps);

            ivl = nivl; ef = nef; reps = nreps;
        }

#pragma unroll
        for (int j = 0; j < PF; ++j) r[j] = rn[j];
    }

    // final_state appended after the per-step outputs
    float* f = out + (size_t)SEQ * ostride + (size_t)b * 3;
    f[0] = ivl;
    f[1] = ef;
    f[2] = reps;
}

extern "C" void kernel_launch(void* const* d_in, const int* in_sizes, int n_in,
                              void* d_out, int out_size) {
    const float* in = (const float*)d_in[0];
    const float* w  = (const float*)d_in[1];
    float* out = (float*)d_out;

    const int batch = in_sizes[0] / (SEQ * 2);
    const int grid = (batch + 31) / 32;

    SM2_31585189494808_kernel<<<grid, 32>>>(in, w, out, batch);
}